// round 1
// baseline (speedup 1.0000x reference)
#include <cuda_runtime.h>
#include <math.h>
#include <stdint.h>

#define N_NODES 50000
#define N_EDGES 800000
#define F_NODE 128
#define HDIM 64
#define NQ 50

// ---------------- scratch (static device memory; no allocations) ----------------
__device__ float g_hlhr[(size_t)N_NODES * 128];  // [hl | hr] per node (also reused as scorer t)
__device__ float g_h[(size_t)N_NODES * 64];      // current node features
__device__ float g_s[N_NODES];                   // scalar scores
__device__ float g_bias0[128];                   // [c_l0 | c_r0 + b0]
__device__ int   g_deg[N_NODES];
__device__ int   g_off[N_NODES + 1];
__device__ int   g_cur[N_NODES];
__device__ int   g_csr[N_EDGES];
__device__ float g_pmax[256];
__device__ float g_psum[3 * 256];
__device__ float g_scal[4];                      // gmax, sum, sumx, sumy

// ---------------- encoder: z_q and layer-0 constant bias ----------------
__global__ void enc_kernel(const int* __restrict__ ap, const float* __restrict__ rssi,
                           const float* __restrict__ emb, const float* __restrict__ ew,
                           const float* __restrict__ eb,
                           const float* __restrict__ Wl0, const float* __restrict__ Wr0,
                           const float* __restrict__ b0)
{
    __shared__ float zq[64];
    int j = threadIdx.x;
    if (j < 64) {
        float zs = 0.f;
        for (int q = 0; q < NQ; q++) {
            float a = eb[j];
            const float* er = emb + (size_t)ap[q] * 32;
            #pragma unroll
            for (int k = 0; k < 32; k++) a += er[k] * ew[k * 64 + j];
            a += rssi[q] * ew[32 * 64 + j];
            zs += fmaxf(a, 0.f);
        }
        zq[j] = zs * (1.f / (float)NQ);
    }
    __syncthreads();
    if (j < 64) {
        float cl = 0.f, cr = 0.f;
        #pragma unroll 8
        for (int t = 0; t < 64; t++) {
            float z = zq[t];
            cl += z * Wl0[(128 + t) * 64 + j];
            cr += z * Wr0[(128 + t) * 64 + j];
        }
        g_bias0[j] = cl;
        g_bias0[64 + j] = cr + b0[j];
    }
}

// ---------------- CSR construction ----------------
__global__ void zero_kernel()
{
    for (int i = blockIdx.x * blockDim.x + threadIdx.x; i < N_NODES; i += gridDim.x * blockDim.x)
        g_deg[i] = 0;
}

__global__ void hist_kernel(const int* __restrict__ ei)
{
    for (int e = blockIdx.x * blockDim.x + threadIdx.x; e < N_EDGES; e += gridDim.x * blockDim.x)
        atomicAdd(&g_deg[ei[N_EDGES + e]], 1);
}

__global__ void scan_kernel()
{
    const int C = (N_NODES + 1023) / 1024;
    int t = threadIdx.x;
    int base = t * C;
    int s = 0;
    for (int i = 0; i < C; i++) {
        int idx = base + i;
        if (idx < N_NODES) s += g_deg[idx];
    }
    __shared__ int ps[1024];
    ps[t] = s;
    __syncthreads();
    for (int off = 1; off < 1024; off <<= 1) {
        int v = (t >= off) ? ps[t - off] : 0;
        __syncthreads();
        ps[t] += v;
        __syncthreads();
    }
    int run = (t > 0) ? ps[t - 1] : 0;
    for (int i = 0; i < C; i++) {
        int idx = base + i;
        if (idx < N_NODES) {
            g_off[idx] = run;
            g_cur[idx] = run;
            run += g_deg[idx];
        }
    }
    if (t == 1023) g_off[N_NODES] = ps[1023];
}

__global__ void fill_kernel(const int* __restrict__ ei)
{
    for (int e = blockIdx.x * blockDim.x + threadIdx.x; e < N_EDGES; e += gridDim.x * blockDim.x) {
        int d = ei[N_EDGES + e];
        int p = atomicAdd(&g_cur[d], 1);
        g_csr[p] = ei[e];
    }
}

// ---------------- fused GEMM: out[n, OUT] = A[n, K] @ [Wl | Wr] + bias ----------------
template<int K, int OUT, bool RELU>
__global__ __launch_bounds__(256) void mm_kernel(
    const float* __restrict__ A, const float* __restrict__ Wl, const float* __restrict__ Wr,
    const float* __restrict__ bias_l, const float* __restrict__ bias_r,
    float* __restrict__ out, int n)
{
    constexpr int ROWS = 64;
    constexpr int CG = OUT / 4;          // column groups (threads along cols)
    constexpr int RG = 256 / CG;         // row groups
    constexpr int R = ROWS / RG;         // rows per thread
    constexpr int APITCH = K + 4;
    constexpr int K4 = K / 4;

    extern __shared__ float sm[];
    float* As = sm;                      // ROWS * APITCH
    float* Ws = sm + ROWS * APITCH;      // K * OUT

    int tid = threadIdx.x;
    int row0 = blockIdx.x * ROWS;

    const float4* A4 = reinterpret_cast<const float4*>(A);
    for (int idx = tid; idx < ROWS * K4; idx += 256) {
        int r = idx / K4, c = idx % K4;
        float4 v = make_float4(0.f, 0.f, 0.f, 0.f);
        if (row0 + r < n) v = A4[(size_t)(row0 + r) * K4 + c];
        *reinterpret_cast<float4*>(&As[r * APITCH + c * 4]) = v;
    }
    for (int idx = tid; idx < K * OUT; idx += 256) {
        int k = idx / OUT, j = idx % OUT;
        float w;
        if (OUT == 64) w = Wl[k * 64 + j];
        else           w = (j < 64) ? Wl[k * 64 + j] : Wr[k * 64 + (j - 64)];
        Ws[idx] = w;
    }
    __syncthreads();

    int ty = tid / CG, tx = tid % CG;
    int r0 = ty * R;
    float acc[R][4];
    #pragma unroll
    for (int i = 0; i < R; i++) { acc[i][0] = acc[i][1] = acc[i][2] = acc[i][3] = 0.f; }

    #pragma unroll 4
    for (int k = 0; k < K; k++) {
        float4 w = *reinterpret_cast<const float4*>(&Ws[k * OUT + tx * 4]);
        #pragma unroll
        for (int i = 0; i < R; i++) {
            float a = As[(r0 + i) * APITCH + k];
            acc[i][0] += a * w.x; acc[i][1] += a * w.y;
            acc[i][2] += a * w.z; acc[i][3] += a * w.w;
        }
    }

    int j0 = tx * 4;
    float b[4];
    #pragma unroll
    for (int q = 0; q < 4; q++) {
        int j = j0 + q;
        float bb = 0.f;
        if (j < 64) { if (bias_l) bb = bias_l[j]; }
        else        { if (bias_r) bb = bias_r[j - 64]; }
        b[q] = bb;
    }
    #pragma unroll
    for (int i = 0; i < R; i++) {
        int row = row0 + r0 + i;
        if (row < n) {
            float4 o;
            o.x = acc[i][0] + b[0]; o.y = acc[i][1] + b[1];
            o.z = acc[i][2] + b[2]; o.w = acc[i][3] + b[3];
            if (RELU) {
                o.x = fmaxf(o.x, 0.f); o.y = fmaxf(o.y, 0.f);
                o.z = fmaxf(o.z, 0.f); o.w = fmaxf(o.w, 0.f);
            }
            *reinterpret_cast<float4*>(&out[(size_t)row * OUT + j0]) = o;
        }
    }
}

// ---------------- aggregation: h_out = relu(mean_{src in N(dst)} hl[src] + hr[dst]) ----------------
__global__ void agg_kernel(const float* __restrict__ hlhr, float* __restrict__ hout)
{
    int w = (blockIdx.x * blockDim.x + threadIdx.x) >> 5;
    int lane = threadIdx.x & 31;
    if (w >= N_NODES) return;
    int s = g_off[w], e = g_off[w + 1];
    float ax = 0.f, ay = 0.f;
    for (int i = s; i < e; i++) {
        int src = g_csr[i];
        float2 v = *reinterpret_cast<const float2*>(&hlhr[(size_t)src * 128 + lane * 2]);
        ax += v.x; ay += v.y;
    }
    int d = e - s;
    float inv = 1.f / (float)(d > 1 ? d : 1);
    float2 hr = *reinterpret_cast<const float2*>(&hlhr[(size_t)w * 128 + 64 + lane * 2]);
    float ox = fmaxf(ax * inv + hr.x, 0.f);
    float oy = fmaxf(ay * inv + hr.y, 0.f);
    *reinterpret_cast<float2*>(&hout[(size_t)w * 64 + lane * 2]) = make_float2(ox, oy);
}

// ---------------- scorer stage 2: s[i] = t[i] . w2 + b2 ----------------
__global__ void score_kernel(const float* __restrict__ t, const float* __restrict__ w2,
                             const float* __restrict__ b2)
{
    int w = (blockIdx.x * blockDim.x + threadIdx.x) >> 5;
    int lane = threadIdx.x & 31;
    if (w >= N_NODES) return;
    float v = t[(size_t)w * 64 + lane] * w2[lane] + t[(size_t)w * 64 + lane + 32] * w2[lane + 32];
    #pragma unroll
    for (int o = 16; o; o >>= 1) v += __shfl_down_sync(0xFFFFFFFFu, v, o);
    if (lane == 0) g_s[w] = v + b2[0];
}

// ---------------- softmax reductions ----------------
__global__ void max1_kernel()
{
    float m = -INFINITY;
    for (int i = blockIdx.x * blockDim.x + threadIdx.x; i < N_NODES; i += gridDim.x * blockDim.x)
        m = fmaxf(m, g_s[i]);
    __shared__ float smx[256];
    smx[threadIdx.x] = m;
    __syncthreads();
    for (int o = 128; o; o >>= 1) {
        if (threadIdx.x < o) smx[threadIdx.x] = fmaxf(smx[threadIdx.x], smx[threadIdx.x + o]);
        __syncthreads();
    }
    if (threadIdx.x == 0) g_pmax[blockIdx.x] = smx[0];
}

__global__ void max2_kernel(int nb)
{
    float m = (threadIdx.x < nb) ? g_pmax[threadIdx.x] : -INFINITY;
    __shared__ float smx[256];
    smx[threadIdx.x] = m;
    __syncthreads();
    for (int o = 128; o; o >>= 1) {
        if (threadIdx.x < o) smx[threadIdx.x] = fmaxf(smx[threadIdx.x], smx[threadIdx.x + o]);
        __syncthreads();
    }
    if (threadIdx.x == 0) g_scal[0] = smx[0];
}

__global__ void exp_kernel(const float* __restrict__ pos, float* __restrict__ out)
{
    float gm = g_scal[0];
    float sum = 0.f, sx = 0.f, sy = 0.f;
    for (int i = blockIdx.x * blockDim.x + threadIdx.x; i < N_NODES; i += gridDim.x * blockDim.x) {
        float e = __expf(g_s[i] - gm);
        out[2 + i] = e;
        sum += e;
        sx += e * pos[2 * i];
        sy += e * pos[2 * i + 1];
    }
    __shared__ float sh[3][256];
    sh[0][threadIdx.x] = sum; sh[1][threadIdx.x] = sx; sh[2][threadIdx.x] = sy;
    __syncthreads();
    for (int o = 128; o; o >>= 1) {
        if (threadIdx.x < o) {
            sh[0][threadIdx.x] += sh[0][threadIdx.x + o];
            sh[1][threadIdx.x] += sh[1][threadIdx.x + o];
            sh[2][threadIdx.x] += sh[2][threadIdx.x + o];
        }
        __syncthreads();
    }
    if (threadIdx.x == 0) {
        g_psum[blockIdx.x] = sh[0][0];
        g_psum[256 + blockIdx.x] = sh[1][0];
        g_psum[512 + blockIdx.x] = sh[2][0];
    }
}

__global__ void sum2_kernel(int nb)
{
    __shared__ float sh[3][256];
    int t = threadIdx.x;
    sh[0][t] = (t < nb) ? g_psum[t] : 0.f;
    sh[1][t] = (t < nb) ? g_psum[256 + t] : 0.f;
    sh[2][t] = (t < nb) ? g_psum[512 + t] : 0.f;
    __syncthreads();
    for (int o = 128; o; o >>= 1) {
        if (t < o) {
            sh[0][t] += sh[0][t + o];
            sh[1][t] += sh[1][t + o];
            sh[2][t] += sh[2][t + o];
        }
        __syncthreads();
    }
    if (t == 0) { g_scal[1] = sh[0][0]; g_scal[2] = sh[1][0]; g_scal[3] = sh[2][0]; }
}

__global__ void norm_kernel(float* __restrict__ out)
{
    float inv = 1.f / g_scal[1];
    for (int i = blockIdx.x * blockDim.x + threadIdx.x; i < N_NODES; i += gridDim.x * blockDim.x)
        out[2 + i] *= inv;
    if (blockIdx.x == 0 && threadIdx.x == 0) {
        out[0] = g_scal[2] * inv;
        out[1] = g_scal[3] * inv;
    }
}

// ---------------- launcher ----------------
extern "C" void kernel_launch(void* const* d_in, const int* in_sizes, int n_in,
                              void* d_out, int out_size)
{
    const float* x     = (const float*)d_in[0];
    const float* pos   = (const float*)d_in[1];
    const int*   ei    = (const int*)d_in[2];
    const int*   ap    = (const int*)d_in[3];
    const float* rssi  = (const float*)d_in[4];
    const float* emb   = (const float*)d_in[5];
    const float* ew    = (const float*)d_in[6];
    const float* eb    = (const float*)d_in[7];
    const float* Wl0   = (const float*)d_in[8];
    const float* Wr0   = (const float*)d_in[9];
    const float* b0    = (const float*)d_in[10];
    const float* Wl1   = (const float*)d_in[11];
    const float* Wr1   = (const float*)d_in[12];
    const float* b1    = (const float*)d_in[13];
    const float* Wl2   = (const float*)d_in[14];
    const float* Wr2   = (const float*)d_in[15];
    const float* b2    = (const float*)d_in[16];
    const float* sc_w1 = (const float*)d_in[17];
    const float* sc_b1 = (const float*)d_in[18];
    const float* sc_w2 = (const float*)d_in[19];
    const float* sc_b2 = (const float*)d_in[20];
    float* out = (float*)d_out;

    // dynamic shared sizes
    const int SM_128_128 = (64 * (128 + 4) + 128 * 128) * 4;  // 99328
    const int SM_64_128  = (64 * (64 + 4) + 64 * 128) * 4;    // 50176
    const int SM_64_64   = (64 * (64 + 4) + 64 * 64) * 4;     // 33792

    cudaFuncSetAttribute(mm_kernel<128, 128, false>, cudaFuncAttributeMaxDynamicSharedMemorySize, SM_128_128);
    cudaFuncSetAttribute(mm_kernel<64, 128, false>,  cudaFuncAttributeMaxDynamicSharedMemorySize, SM_64_128);
    cudaFuncSetAttribute(mm_kernel<64, 64, true>,    cudaFuncAttributeMaxDynamicSharedMemorySize, SM_64_64);

    float* hlhr; float* h; float* bias0;
    cudaGetSymbolAddress((void**)&hlhr, g_hlhr);
    cudaGetSymbolAddress((void**)&h, g_h);
    cudaGetSymbolAddress((void**)&bias0, g_bias0);

    const int MB = (N_NODES + 63) / 64;            // 782 blocks for GEMMs
    const int WB = (N_NODES * 32 + 255) / 256;     // warp-per-node grids
    const int EB = (N_EDGES + 255) / 256;

    enc_kernel<<<1, 64>>>(ap, rssi, emb, ew, eb, Wl0, Wr0, b0);
    zero_kernel<<<196, 256>>>();
    hist_kernel<<<EB, 256>>>(ei);
    scan_kernel<<<1, 1024>>>();
    fill_kernel<<<EB, 256>>>(ei);

    // layer 0 (h0 = [x | z_q] folded into bias)
    mm_kernel<128, 128, false><<<MB, 256, SM_128_128>>>(x, Wl0, Wr0, bias0, bias0 + 64, hlhr, N_NODES);
    agg_kernel<<<WB, 256>>>(hlhr, h);
    // layer 1
    mm_kernel<64, 128, false><<<MB, 256, SM_64_128>>>(h, Wl1, Wr1, nullptr, b1, hlhr, N_NODES);
    agg_kernel<<<WB, 256>>>(hlhr, h);
    // layer 2
    mm_kernel<64, 128, false><<<MB, 256, SM_64_128>>>(h, Wl2, Wr2, nullptr, b2, hlhr, N_NODES);
    agg_kernel<<<WB, 256>>>(hlhr, h);
    // scorer
    mm_kernel<64, 64, true><<<MB, 256, SM_64_64>>>(h, sc_w1, nullptr, sc_b1, nullptr, hlhr, N_NODES);
    score_kernel<<<WB, 256>>>(hlhr, sc_w2, sc_b2);

    // softmax + weighted position
    max1_kernel<<<128, 256>>>();
    max2_kernel<<<1, 256>>>(128);
    exp_kernel<<<128, 256>>>(pos, out);
    sum2_kernel<<<1, 256>>>(128);
    norm_kernel<<<196, 256>>>(out);
}

// round 2
// speedup vs baseline: 1.2092x; 1.2092x over previous
#include <cuda_runtime.h>
#include <math.h>
#include <stdint.h>

#define N_NODES 50000
#define N_EDGES 800000
#define NQ 50
#define NBS 196   // scan blocks: 196*256 >= 50000

// ---------------- scratch (static device memory; no allocations) ----------------
__device__ float g_hlhr[(size_t)N_NODES * 128];  // [hl | hr] per node (also reused as scorer t)
__device__ float g_h[(size_t)N_NODES * 64];      // current node features
__device__ float g_s[N_NODES];                   // scalar scores
__device__ float g_bias0[128];                   // [c_l0 | c_r0 + b0]
__device__ int   g_deg[N_NODES];
__device__ int   g_off[N_NODES + 1];
__device__ int   g_cur[N_NODES];
__device__ int   g_csr[N_EDGES];
__device__ int   g_part[NBS];
__device__ float g_pmax[256];
__device__ float g_psum[3 * 256];
__device__ float g_scal[4];                      // gmax, sum, sumx, sumy

// ---------------- f32x2 packed helpers ----------------
__device__ __forceinline__ unsigned long long f32x2_fma(unsigned long long a,
                                                        unsigned long long b,
                                                        unsigned long long c)
{
    unsigned long long d;
    asm("fma.rn.f32x2 %0, %1, %2, %3;" : "=l"(d) : "l"(a), "l"(b), "l"(c));
    return d;
}
__device__ __forceinline__ unsigned long long f32x2_dup(float w)
{
    unsigned long long d;
    asm("mov.b64 %0, {%1, %1};" : "=l"(d) : "f"(w));
    return d;
}
__device__ __forceinline__ void f32x2_unpack(unsigned long long v, float& lo, float& hi)
{
    asm("mov.b64 {%0, %1}, %2;" : "=f"(lo), "=f"(hi) : "l"(v));
}

// ---------------- encoder: z_q and layer-0 constant bias ----------------
__global__ void enc_kernel(const int* __restrict__ ap, const float* __restrict__ rssi,
                           const float* __restrict__ emb, const float* __restrict__ ew,
                           const float* __restrict__ eb,
                           const float* __restrict__ Wl0, const float* __restrict__ Wr0,
                           const float* __restrict__ b0)
{
    __shared__ float zq[64];
    int j = threadIdx.x;
    if (j < 64) {
        float zs = 0.f;
        for (int q = 0; q < NQ; q++) {
            float a = eb[j];
            const float* er = emb + (size_t)ap[q] * 32;
            #pragma unroll
            for (int k = 0; k < 32; k++) a += er[k] * ew[k * 64 + j];
            a += rssi[q] * ew[32 * 64 + j];
            zs += fmaxf(a, 0.f);
        }
        zq[j] = zs * (1.f / (float)NQ);
    }
    __syncthreads();
    if (j < 64) {
        float cl = 0.f, cr = 0.f;
        #pragma unroll 8
        for (int t = 0; t < 64; t++) {
            float z = zq[t];
            cl += z * Wl0[(128 + t) * 64 + j];
            cr += z * Wr0[(128 + t) * 64 + j];
        }
        g_bias0[j] = cl;
        g_bias0[64 + j] = cr + b0[j];
    }
}

// ---------------- CSR construction ----------------
__global__ void zero_kernel()
{
    for (int i = blockIdx.x * blockDim.x + threadIdx.x; i < N_NODES; i += gridDim.x * blockDim.x)
        g_deg[i] = 0;
}

__global__ void hist_kernel(const int* __restrict__ ei)
{
    for (int e = blockIdx.x * blockDim.x + threadIdx.x; e < N_EDGES; e += gridDim.x * blockDim.x)
        atomicAdd(&g_deg[ei[N_EDGES + e]], 1);
}

// stage 1: per-block sums of g_deg
__global__ void scan1_kernel()
{
    int t = threadIdx.x;
    int i = blockIdx.x * 256 + t;
    int v = (i < N_NODES) ? g_deg[i] : 0;
    __shared__ int sh[256];
    sh[t] = v;
    __syncthreads();
    #pragma unroll
    for (int o = 128; o; o >>= 1) {
        if (t < o) sh[t] += sh[t + o];
        __syncthreads();
    }
    if (t == 0) g_part[blockIdx.x] = sh[0];
}

// stage 2: exclusive scan of NBS partials (single small block)
__global__ void scan2_kernel()
{
    int t = threadIdx.x;
    int v = (t < NBS) ? g_part[t] : 0;
    __shared__ int ps[256];
    ps[t] = v;
    __syncthreads();
    #pragma unroll
    for (int o = 1; o < 256; o <<= 1) {
        int add = (t >= o) ? ps[t - o] : 0;
        __syncthreads();
        ps[t] += add;
        __syncthreads();
    }
    if (t < NBS) g_part[t] = ps[t] - v;   // exclusive
    if (t == 0) g_off[N_NODES] = N_EDGES; // every edge counted
}

// stage 3: per-block exclusive scan + base -> g_off, g_cur
__global__ void scan3_kernel()
{
    int t = threadIdx.x;
    int i = blockIdx.x * 256 + t;
    int v = (i < N_NODES) ? g_deg[i] : 0;
    __shared__ int ps[256];
    ps[t] = v;
    __syncthreads();
    #pragma unroll
    for (int o = 1; o < 256; o <<= 1) {
        int add = (t >= o) ? ps[t - o] : 0;
        __syncthreads();
        ps[t] += add;
        __syncthreads();
    }
    if (i < N_NODES) {
        int off = g_part[blockIdx.x] + ps[t] - v;
        g_off[i] = off;
        g_cur[i] = off;
    }
}

__global__ void fill_kernel(const int* __restrict__ ei)
{
    for (int e = blockIdx.x * blockDim.x + threadIdx.x; e < N_EDGES; e += gridDim.x * blockDim.x) {
        int d = ei[N_EDGES + e];
        int p = atomicAdd(&g_cur[d], 1);
        g_csr[p] = ei[e];
    }
}

// ---------------- fused GEMM with packed f32x2 FMA ----------------
// out[n, OUT] = A[n, K] @ [Wl | Wr] + bias ; A tile stored k-major in smem
template<int K, int OUT, bool RELU>
__global__ __launch_bounds__(256) void mm_kernel(
    const float* __restrict__ A, const float* __restrict__ Wl, const float* __restrict__ Wr,
    const float* __restrict__ bias_l, const float* __restrict__ bias_r,
    float* __restrict__ out, int n)
{
    constexpr int ROWS = 64;
    constexpr int CG = OUT / 4;          // threads along cols (4 cols each)
    constexpr int RG = 256 / CG;         // row groups
    constexpr int R = ROWS / RG;         // rows per thread
    constexpr int RP = R / 2;            // row pairs (f32x2)
    constexpr int PITCH = ROWS + 2;      // 66: even -> 8B-aligned row pairs
    constexpr int K4 = K / 4;

    extern __shared__ float sm[];
    float* As = sm;                      // K * PITCH, transposed: As[k*PITCH + r]
    float* Ws = sm + K * PITCH;          // K * OUT

    int tid = threadIdx.x;
    int row0 = blockIdx.x * ROWS;

    const float4* A4 = reinterpret_cast<const float4*>(A);
    for (int idx = tid; idx < ROWS * K4; idx += 256) {
        int r = idx / K4, c = idx % K4;
        float4 v = make_float4(0.f, 0.f, 0.f, 0.f);
        if (row0 + r < n) v = A4[(size_t)(row0 + r) * K4 + c];
        As[(4 * c + 0) * PITCH + r] = v.x;
        As[(4 * c + 1) * PITCH + r] = v.y;
        As[(4 * c + 2) * PITCH + r] = v.z;
        As[(4 * c + 3) * PITCH + r] = v.w;
    }
    for (int idx = tid; idx < K * OUT; idx += 256) {
        int k = idx / OUT, j = idx % OUT;
        float w;
        if (OUT == 64) w = Wl[k * 64 + j];
        else           w = (j < 64) ? Wl[k * 64 + j] : Wr[k * 64 + (j - 64)];
        Ws[idx] = w;
    }
    __syncthreads();

    int ty = tid / CG, tx = tid % CG;
    int r0 = ty * R;
    int j0 = tx * 4;

    unsigned long long acc[RP][4];
    #pragma unroll
    for (int i = 0; i < RP; i++) {
        acc[i][0] = acc[i][1] = acc[i][2] = acc[i][3] = 0ULL;
    }

    #pragma unroll 2
    for (int k = 0; k < K; k++) {
        float4 w = *reinterpret_cast<const float4*>(&Ws[k * OUT + j0]);
        unsigned long long w2[4];
        w2[0] = f32x2_dup(w.x); w2[1] = f32x2_dup(w.y);
        w2[2] = f32x2_dup(w.z); w2[3] = f32x2_dup(w.w);
        const unsigned long long* ap =
            reinterpret_cast<const unsigned long long*>(&As[k * PITCH + r0]);
        #pragma unroll
        for (int rp = 0; rp < RP; rp++) {
            unsigned long long a2 = ap[rp];
            acc[rp][0] = f32x2_fma(a2, w2[0], acc[rp][0]);
            acc[rp][1] = f32x2_fma(a2, w2[1], acc[rp][1]);
            acc[rp][2] = f32x2_fma(a2, w2[2], acc[rp][2]);
            acc[rp][3] = f32x2_fma(a2, w2[3], acc[rp][3]);
        }
    }

    float b[4];
    #pragma unroll
    for (int q = 0; q < 4; q++) {
        int j = j0 + q;
        float bb = 0.f;
        if (j < 64) { if (bias_l) bb = bias_l[j]; }
        else        { if (bias_r) bb = bias_r[j - 64]; }
        b[q] = bb;
    }

    #pragma unroll
    for (int rp = 0; rp < RP; rp++) {
        float lo[4], hi[4];
        #pragma unroll
        for (int q = 0; q < 4; q++) f32x2_unpack(acc[rp][q], lo[q], hi[q]);
        int rowA = row0 + r0 + 2 * rp;
        int rowB = rowA + 1;
        if (rowA < n) {
            float4 o;
            o.x = lo[0] + b[0]; o.y = lo[1] + b[1]; o.z = lo[2] + b[2]; o.w = lo[3] + b[3];
            if (RELU) { o.x = fmaxf(o.x, 0.f); o.y = fmaxf(o.y, 0.f); o.z = fmaxf(o.z, 0.f); o.w = fmaxf(o.w, 0.f); }
            *reinterpret_cast<float4*>(&out[(size_t)rowA * OUT + j0]) = o;
        }
        if (rowB < n) {
            float4 o;
            o.x = hi[0] + b[0]; o.y = hi[1] + b[1]; o.z = hi[2] + b[2]; o.w = hi[3] + b[3];
            if (RELU) { o.x = fmaxf(o.x, 0.f); o.y = fmaxf(o.y, 0.f); o.z = fmaxf(o.z, 0.f); o.w = fmaxf(o.w, 0.f); }
            *reinterpret_cast<float4*>(&out[(size_t)rowB * OUT + j0]) = o;
        }
    }
}

// ---------------- aggregation: h_out = relu(mean_{src in N(dst)} hl[src] + hr[dst]) ----------------
__global__ void agg_kernel(const float* __restrict__ hlhr, float* __restrict__ hout)
{
    int w = (blockIdx.x * blockDim.x + threadIdx.x) >> 5;
    int lane = threadIdx.x & 31;
    if (w >= N_NODES) return;
    int s = g_off[w], e = g_off[w + 1];
    float ax = 0.f, ay = 0.f;
    int i = s;
    for (; i + 1 < e; i += 2) {
        int s0 = g_csr[i], s1 = g_csr[i + 1];
        float2 v0 = *reinterpret_cast<const float2*>(&hlhr[(size_t)s0 * 128 + lane * 2]);
        float2 v1 = *reinterpret_cast<const float2*>(&hlhr[(size_t)s1 * 128 + lane * 2]);
        ax += v0.x + v1.x; ay += v0.y + v1.y;
    }
    if (i < e) {
        int s0 = g_csr[i];
        float2 v0 = *reinterpret_cast<const float2*>(&hlhr[(size_t)s0 * 128 + lane * 2]);
        ax += v0.x; ay += v0.y;
    }
    int d = e - s;
    float inv = 1.f / (float)(d > 1 ? d : 1);
    float2 hr = *reinterpret_cast<const float2*>(&hlhr[(size_t)w * 128 + 64 + lane * 2]);
    float ox = fmaxf(ax * inv + hr.x, 0.f);
    float oy = fmaxf(ay * inv + hr.y, 0.f);
    *reinterpret_cast<float2*>(&hout[(size_t)w * 64 + lane * 2]) = make_float2(ox, oy);
}

// ---------------- scorer stage 2: s[i] = t[i] . w2 + b2 ----------------
__global__ void score_kernel(const float* __restrict__ t, const float* __restrict__ w2,
                             const float* __restrict__ b2)
{
    int w = (blockIdx.x * blockDim.x + threadIdx.x) >> 5;
    int lane = threadIdx.x & 31;
    if (w >= N_NODES) return;
    float v = t[(size_t)w * 64 + lane] * w2[lane] + t[(size_t)w * 64 + lane + 32] * w2[lane + 32];
    #pragma unroll
    for (int o = 16; o; o >>= 1) v += __shfl_down_sync(0xFFFFFFFFu, v, o);
    if (lane == 0) g_s[w] = v + b2[0];
}

// ---------------- softmax reductions ----------------
__global__ void max1_kernel()
{
    float m = -INFINITY;
    for (int i = blockIdx.x * blockDim.x + threadIdx.x; i < N_NODES; i += gridDim.x * blockDim.x)
        m = fmaxf(m, g_s[i]);
    __shared__ float smx[256];
    smx[threadIdx.x] = m;
    __syncthreads();
    for (int o = 128; o; o >>= 1) {
        if (threadIdx.x < o) smx[threadIdx.x] = fmaxf(smx[threadIdx.x], smx[threadIdx.x + o]);
        __syncthreads();
    }
    if (threadIdx.x == 0) g_pmax[blockIdx.x] = smx[0];
}

__global__ void max2_kernel(int nb)
{
    float m = (threadIdx.x < nb) ? g_pmax[threadIdx.x] : -INFINITY;
    __shared__ float smx[256];
    smx[threadIdx.x] = m;
    __syncthreads();
    for (int o = 128; o; o >>= 1) {
        if (threadIdx.x < o) smx[threadIdx.x] = fmaxf(smx[threadIdx.x], smx[threadIdx.x + o]);
        __syncthreads();
    }
    if (threadIdx.x == 0) g_scal[0] = smx[0];
}

__global__ void exp_kernel(const float* __restrict__ pos, float* __restrict__ out)
{
    float gm = g_scal[0];
    float sum = 0.f, sx = 0.f, sy = 0.f;
    for (int i = blockIdx.x * blockDim.x + threadIdx.x; i < N_NODES; i += gridDim.x * blockDim.x) {
        float e = __expf(g_s[i] - gm);
        out[2 + i] = e;
        sum += e;
        sx += e * pos[2 * i];
        sy += e * pos[2 * i + 1];
    }
    __shared__ float sh[3][256];
    sh[0][threadIdx.x] = sum; sh[1][threadIdx.x] = sx; sh[2][threadIdx.x] = sy;
    __syncthreads();
    for (int o = 128; o; o >>= 1) {
        if (threadIdx.x < o) {
            sh[0][threadIdx.x] += sh[0][threadIdx.x + o];
            sh[1][threadIdx.x] += sh[1][threadIdx.x + o];
            sh[2][threadIdx.x] += sh[2][threadIdx.x + o];
        }
        __syncthreads();
    }
    if (threadIdx.x == 0) {
        g_psum[blockIdx.x] = sh[0][0];
        g_psum[256 + blockIdx.x] = sh[1][0];
        g_psum[512 + blockIdx.x] = sh[2][0];
    }
}

__global__ void sum2_kernel(int nb)
{
    __shared__ float sh[3][256];
    int t = threadIdx.x;
    sh[0][t] = (t < nb) ? g_psum[t] : 0.f;
    sh[1][t] = (t < nb) ? g_psum[256 + t] : 0.f;
    sh[2][t] = (t < nb) ? g_psum[512 + t] : 0.f;
    __syncthreads();
    for (int o = 128; o; o >>= 1) {
        if (t < o) {
            sh[0][t] += sh[0][t + o];
            sh[1][t] += sh[1][t + o];
            sh[2][t] += sh[2][t + o];
        }
        __syncthreads();
    }
    if (t == 0) { g_scal[1] = sh[0][0]; g_scal[2] = sh[1][0]; g_scal[3] = sh[2][0]; }
}

__global__ void norm_kernel(float* __restrict__ out)
{
    float inv = 1.f / g_scal[1];
    for (int i = blockIdx.x * blockDim.x + threadIdx.x; i < N_NODES; i += gridDim.x * blockDim.x)
        out[2 + i] *= inv;
    if (blockIdx.x == 0 && threadIdx.x == 0) {
        out[0] = g_scal[2] * inv;
        out[1] = g_scal[3] * inv;
    }
}

// ---------------- launcher ----------------
extern "C" void kernel_launch(void* const* d_in, const int* in_sizes, int n_in,
                              void* d_out, int out_size)
{
    const float* x     = (const float*)d_in[0];
    const float* pos   = (const float*)d_in[1];
    const int*   ei    = (const int*)d_in[2];
    const int*   ap    = (const int*)d_in[3];
    const float* rssi  = (const float*)d_in[4];
    const float* emb   = (const float*)d_in[5];
    const float* ew    = (const float*)d_in[6];
    const float* eb    = (const float*)d_in[7];
    const float* Wl0   = (const float*)d_in[8];
    const float* Wr0   = (const float*)d_in[9];
    const float* b0    = (const float*)d_in[10];
    const float* Wl1   = (const float*)d_in[11];
    const float* Wr1   = (const float*)d_in[12];
    const float* b1    = (const float*)d_in[13];
    const float* Wl2   = (const float*)d_in[14];
    const float* Wr2   = (const float*)d_in[15];
    const float* b2    = (const float*)d_in[16];
    const float* sc_w1 = (const float*)d_in[17];
    const float* sc_b1 = (const float*)d_in[18];
    const float* sc_w2 = (const float*)d_in[19];
    const float* sc_b2 = (const float*)d_in[20];
    float* out = (float*)d_out;

    // dynamic shared sizes (As = K*66, Ws = K*OUT floats)
    const int SM_128_128 = (128 * 66 + 128 * 128) * 4;  // 99328
    const int SM_64_128  = (64 * 66 + 64 * 128) * 4;    // 49664
    const int SM_64_64   = (64 * 66 + 64 * 64) * 4;     // 33280

    cudaFuncSetAttribute(mm_kernel<128, 128, false>, cudaFuncAttributeMaxDynamicSharedMemorySize, SM_128_128);
    cudaFuncSetAttribute(mm_kernel<64, 128, false>,  cudaFuncAttributeMaxDynamicSharedMemorySize, SM_64_128);
    cudaFuncSetAttribute(mm_kernel<64, 64, true>,    cudaFuncAttributeMaxDynamicSharedMemorySize, SM_64_64);

    float* hlhr; float* h; float* bias0;
    cudaGetSymbolAddress((void**)&hlhr, g_hlhr);
    cudaGetSymbolAddress((void**)&h, g_h);
    cudaGetSymbolAddress((void**)&bias0, g_bias0);

    const int MB = (N_NODES + 63) / 64;            // 782 blocks for GEMMs
    const int WB = (N_NODES * 32 + 255) / 256;     // warp-per-node grids
    const int EB = (N_EDGES + 255) / 256;

    enc_kernel<<<1, 64>>>(ap, rssi, emb, ew, eb, Wl0, Wr0, b0);
    zero_kernel<<<196, 256>>>();
    hist_kernel<<<EB, 256>>>(ei);
    scan1_kernel<<<NBS, 256>>>();
    scan2_kernel<<<1, 256>>>();
    scan3_kernel<<<NBS, 256>>>();
    fill_kernel<<<EB, 256>>>(ei);

    // layer 0 (h0 = [x | z_q] folded into bias)
    mm_kernel<128, 128, false><<<MB, 256, SM_128_128>>>(x, Wl0, Wr0, bias0, bias0 + 64, hlhr, N_NODES);
    agg_kernel<<<WB, 256>>>(hlhr, h);
    // layer 1
    mm_kernel<64, 128, false><<<MB, 256, SM_64_128>>>(h, Wl1, Wr1, nullptr, b1, hlhr, N_NODES);
    agg_kernel<<<WB, 256>>>(hlhr, h);
    // layer 2
    mm_kernel<64, 128, false><<<MB, 256, SM_64_128>>>(h, Wl2, Wr2, nullptr, b2, hlhr, N_NODES);
    agg_kernel<<<WB, 256>>>(hlhr, h);
    // scorer
    mm_kernel<64, 64, true><<<MB, 256, SM_64_64>>>(h, sc_w1, nullptr, sc_b1, nullptr, hlhr, N_NODES);
    score_kernel<<<WB, 256>>>(hlhr, sc_w2, sc_b2);

    // softmax + weighted position
    max1_kernel<<<128, 256>>>();
    max2_kernel<<<1, 256>>>(128);
    exp_kernel<<<128, 256>>>(pos, out);
    sum2_kernel<<<1, 256>>>(128);
    norm_kernel<<<196, 256>>>(out);
}

// round 3
// speedup vs baseline: 1.2772x; 1.0563x over previous
#include <cuda_runtime.h>
#include <math.h>
#include <stdint.h>

#define N_NODES 50000
#define N_EDGES 800000
#define NQ 50
#define NBS 196   // scan blocks: 196*256 >= 50000

// ---------------- scratch (static device memory; no allocations) ----------------
__device__ float g_hlhr[(size_t)N_NODES * 128];  // [hl | hr] per node
__device__ float g_h[(size_t)N_NODES * 64];      // current node features
__device__ float g_s[N_NODES];                   // scalar scores
__device__ float g_bias0[128];                   // [c_l0 | c_r0 + b0]
__device__ int   g_deg[N_NODES];
__device__ int   g_off[N_NODES + 1];
__device__ int   g_cur[N_NODES];
__device__ int   g_csr[N_EDGES];
__device__ int   g_part[NBS];
__device__ unsigned int g_smax_bits;             // monotone-encoded float max
__device__ float g_psum[3 * 256];

// ---------------- monotone float<->uint encoding (for deterministic atomicMax) --
__device__ __forceinline__ unsigned int enc_f(float f)
{
    unsigned int u = __float_as_uint(f);
    return (u & 0x80000000u) ? ~u : (u | 0x80000000u);
}
__device__ __forceinline__ float dec_f(unsigned int u)
{
    return (u & 0x80000000u) ? __uint_as_float(u & 0x7FFFFFFFu) : __uint_as_float(~u);
}

// ---------------- f32x2 packed helpers ----------------
__device__ __forceinline__ unsigned long long f32x2_fma(unsigned long long a,
                                                        unsigned long long b,
                                                        unsigned long long c)
{
    unsigned long long d;
    asm("fma.rn.f32x2 %0, %1, %2, %3;" : "=l"(d) : "l"(a), "l"(b), "l"(c));
    return d;
}
__device__ __forceinline__ unsigned long long f32x2_dup(float w)
{
    unsigned long long d;
    asm("mov.b64 %0, {%1, %1};" : "=l"(d) : "f"(w));
    return d;
}
__device__ __forceinline__ void f32x2_unpack(unsigned long long v, float& lo, float& hi)
{
    asm("mov.b64 {%0, %1}, %2;" : "=f"(lo), "=f"(hi) : "l"(v));
}

// ---------------- init: zero deg + smax, block 0 also does encoder ----------------
__global__ void init_kernel(const int* __restrict__ ap, const float* __restrict__ rssi,
                            const float* __restrict__ emb, const float* __restrict__ ew,
                            const float* __restrict__ eb,
                            const float* __restrict__ Wl0, const float* __restrict__ Wr0,
                            const float* __restrict__ b0)
{
    int i = blockIdx.x * 256 + threadIdx.x;
    if (i < N_NODES) g_deg[i] = 0;

    if (blockIdx.x == 0) {
        if (threadIdx.x == 0) g_smax_bits = 0u;  // encoded ~ -inf
        __shared__ float zq[64];
        int j = threadIdx.x;
        if (j < 64) {
            float zs = 0.f;
            for (int q = 0; q < NQ; q++) {
                float a = eb[j];
                const float* er = emb + (size_t)ap[q] * 32;
                #pragma unroll
                for (int k = 0; k < 32; k++) a += er[k] * ew[k * 64 + j];
                a += rssi[q] * ew[32 * 64 + j];
                zs += fmaxf(a, 0.f);
            }
            zq[j] = zs * (1.f / (float)NQ);
        }
        __syncthreads();
        if (j < 64) {
            float cl = 0.f, cr = 0.f;
            #pragma unroll 8
            for (int t = 0; t < 64; t++) {
                float z = zq[t];
                cl += z * Wl0[(128 + t) * 64 + j];
                cr += z * Wr0[(128 + t) * 64 + j];
            }
            g_bias0[j] = cl;
            g_bias0[64 + j] = cr + b0[j];
        }
    }
}

// ---------------- CSR construction ----------------
__global__ void hist_kernel(const int* __restrict__ ei)
{
    for (int e = blockIdx.x * blockDim.x + threadIdx.x; e < N_EDGES; e += gridDim.x * blockDim.x)
        atomicAdd(&g_deg[ei[N_EDGES + e]], 1);
}

__global__ void scan1_kernel()
{
    int t = threadIdx.x;
    int i = blockIdx.x * 256 + t;
    int v = (i < N_NODES) ? g_deg[i] : 0;
    __shared__ int sh[256];
    sh[t] = v;
    __syncthreads();
    #pragma unroll
    for (int o = 128; o; o >>= 1) {
        if (t < o) sh[t] += sh[t + o];
        __syncthreads();
    }
    if (t == 0) g_part[blockIdx.x] = sh[0];
}

__global__ void scan2_kernel()
{
    int t = threadIdx.x;
    int v = (t < NBS) ? g_part[t] : 0;
    __shared__ int ps[256];
    ps[t] = v;
    __syncthreads();
    #pragma unroll
    for (int o = 1; o < 256; o <<= 1) {
        int add = (t >= o) ? ps[t - o] : 0;
        __syncthreads();
        ps[t] += add;
        __syncthreads();
    }
    if (t < NBS) g_part[t] = ps[t] - v;
    if (t == 0) g_off[N_NODES] = N_EDGES;
}

__global__ void scan3_kernel()
{
    int t = threadIdx.x;
    int i = blockIdx.x * 256 + t;
    int v = (i < N_NODES) ? g_deg[i] : 0;
    __shared__ int ps[256];
    ps[t] = v;
    __syncthreads();
    #pragma unroll
    for (int o = 1; o < 256; o <<= 1) {
        int add = (t >= o) ? ps[t - o] : 0;
        __syncthreads();
        ps[t] += add;
        __syncthreads();
    }
    if (i < N_NODES) {
        int off = g_part[blockIdx.x] + ps[t] - v;
        g_off[i] = off;
        g_cur[i] = off;
    }
}

__global__ void fill_kernel(const int* __restrict__ ei)
{
    for (int e = blockIdx.x * blockDim.x + threadIdx.x; e < N_EDGES; e += gridDim.x * blockDim.x) {
        int d = ei[N_EDGES + e];
        int p = atomicAdd(&g_cur[d], 1);
        g_csr[p] = ei[e];
    }
}

// ---------------- fused GEMM with packed f32x2 FMA ----------------
// out[n, OUT] = A[n, K] @ [Wl | Wr] + bias ; A tile transposed (k-major) in smem
template<int K, int OUT>
__global__ __launch_bounds__(256) void mm_kernel(
    const float* __restrict__ A, const float* __restrict__ Wl, const float* __restrict__ Wr,
    const float* __restrict__ bias_l, const float* __restrict__ bias_r,
    float* __restrict__ out, int n)
{
    constexpr int ROWS = 64;
    constexpr int CG = OUT / 4;          // threads along cols (4 cols each)
    constexpr int RG = 256 / CG;         // row groups
    constexpr int R = ROWS / RG;         // rows per thread
    constexpr int RP = R / 2;            // row pairs (f32x2)
    constexpr int PITCH = ROWS + 4;      // 68: 16B-aligned row quads
    constexpr int K4 = K / 4;

    extern __shared__ float sm[];
    float* As = sm;                      // K * PITCH, As[k*PITCH + r]
    float* Ws = sm + K * PITCH;          // K * OUT

    int tid = threadIdx.x;
    int row0 = blockIdx.x * ROWS;

    const float4* A4 = reinterpret_cast<const float4*>(A);
    for (int idx = tid; idx < ROWS * K4; idx += 256) {
        int r = idx / K4, c = idx % K4;
        float4 v = make_float4(0.f, 0.f, 0.f, 0.f);
        if (row0 + r < n) v = A4[(size_t)(row0 + r) * K4 + c];
        As[(4 * c + 0) * PITCH + r] = v.x;
        As[(4 * c + 1) * PITCH + r] = v.y;
        As[(4 * c + 2) * PITCH + r] = v.z;
        As[(4 * c + 3) * PITCH + r] = v.w;
    }
    for (int idx = tid; idx < K * OUT; idx += 256) {
        int k = idx / OUT, j = idx % OUT;
        float w = (OUT == 64 || j < 64) ? Wl[k * 64 + (j & 63)] : Wr[k * 64 + (j - 64)];
        Ws[idx] = w;
    }
    __syncthreads();

    int ty = tid / CG, tx = tid % CG;
    int r0 = ty * R;                     // multiple of 4 -> 16B aligned
    int j0 = tx * 4;

    unsigned long long acc[RP][4];
    #pragma unroll
    for (int i = 0; i < RP; i++) acc[i][0] = acc[i][1] = acc[i][2] = acc[i][3] = 0ULL;

    #pragma unroll 2
    for (int k = 0; k < K; k++) {
        float4 w = *reinterpret_cast<const float4*>(&Ws[k * OUT + j0]);
        unsigned long long w2[4];
        w2[0] = f32x2_dup(w.x); w2[1] = f32x2_dup(w.y);
        w2[2] = f32x2_dup(w.z); w2[3] = f32x2_dup(w.w);
        const ulonglong2* ap = reinterpret_cast<const ulonglong2*>(&As[k * PITCH + r0]);
        #pragma unroll
        for (int rq = 0; rq < RP / 2; rq++) {
            ulonglong2 a2 = ap[rq];
            acc[2*rq][0] = f32x2_fma(a2.x, w2[0], acc[2*rq][0]);
            acc[2*rq][1] = f32x2_fma(a2.x, w2[1], acc[2*rq][1]);
            acc[2*rq][2] = f32x2_fma(a2.x, w2[2], acc[2*rq][2]);
            acc[2*rq][3] = f32x2_fma(a2.x, w2[3], acc[2*rq][3]);
            acc[2*rq+1][0] = f32x2_fma(a2.y, w2[0], acc[2*rq+1][0]);
            acc[2*rq+1][1] = f32x2_fma(a2.y, w2[1], acc[2*rq+1][1]);
            acc[2*rq+1][2] = f32x2_fma(a2.y, w2[2], acc[2*rq+1][2]);
            acc[2*rq+1][3] = f32x2_fma(a2.y, w2[3], acc[2*rq+1][3]);
        }
    }

    float b[4];
    #pragma unroll
    for (int q = 0; q < 4; q++) {
        int j = j0 + q;
        float bb = 0.f;
        if (j < 64) { if (bias_l) bb = bias_l[j]; }
        else        { if (bias_r) bb = bias_r[j - 64]; }
        b[q] = bb;
    }

    #pragma unroll
    for (int rp = 0; rp < RP; rp++) {
        float lo[4], hi[4];
        #pragma unroll
        for (int q = 0; q < 4; q++) f32x2_unpack(acc[rp][q], lo[q], hi[q]);
        int rowA = row0 + r0 + 2 * rp;
        int rowB = rowA + 1;
        if (rowA < n) {
            float4 o = make_float4(lo[0] + b[0], lo[1] + b[1], lo[2] + b[2], lo[3] + b[3]);
            *reinterpret_cast<float4*>(&out[(size_t)rowA * OUT + j0]) = o;
        }
        if (rowB < n) {
            float4 o = make_float4(hi[0] + b[0], hi[1] + b[1], hi[2] + b[2], hi[3] + b[3]);
            *reinterpret_cast<float4*>(&out[(size_t)rowB * OUT + j0]) = o;
        }
    }
}

// ---------------- fused scorer: s = relu(h@w1 + b1) . w2 ; global max via atomicMax
// (b2 dropped: softmax is shift-invariant)
__global__ __launch_bounds__(256) void mmscore_kernel(
    const float* __restrict__ A, const float* __restrict__ W1,
    const float* __restrict__ b1, const float* __restrict__ w2, int n)
{
    constexpr int K = 64, OUT = 64;
    constexpr int CG = 16;               // threads along cols (4 cols each)
    constexpr int R = 4;                 // rows per thread
    constexpr int PITCH = 68;
    constexpr int K4 = K / 4;

    __shared__ float As[K * PITCH];
    __shared__ float Ws[K * OUT];
    __shared__ unsigned int blkmax;

    int tid = threadIdx.x;
    int row0 = blockIdx.x * 64;
    if (tid == 0) blkmax = 0u;

    const float4* A4 = reinterpret_cast<const float4*>(A);
    for (int idx = tid; idx < 64 * K4; idx += 256) {
        int r = idx / K4, c = idx % K4;
        float4 v = make_float4(0.f, 0.f, 0.f, 0.f);
        if (row0 + r < n) v = A4[(size_t)(row0 + r) * K4 + c];
        As[(4 * c + 0) * PITCH + r] = v.x;
        As[(4 * c + 1) * PITCH + r] = v.y;
        As[(4 * c + 2) * PITCH + r] = v.z;
        As[(4 * c + 3) * PITCH + r] = v.w;
    }
    for (int idx = tid; idx < K * OUT; idx += 256)
        Ws[idx] = W1[idx];
    __syncthreads();

    int ty = tid / CG, tx = tid % CG;
    int r0 = ty * R;
    int j0 = tx * 4;

    unsigned long long acc[2][4];
    #pragma unroll
    for (int i = 0; i < 2; i++) acc[i][0] = acc[i][1] = acc[i][2] = acc[i][3] = 0ULL;

    #pragma unroll 2
    for (int k = 0; k < K; k++) {
        float4 w = *reinterpret_cast<const float4*>(&Ws[k * OUT + j0]);
        unsigned long long w2d[4];
        w2d[0] = f32x2_dup(w.x); w2d[1] = f32x2_dup(w.y);
        w2d[2] = f32x2_dup(w.z); w2d[3] = f32x2_dup(w.w);
        ulonglong2 a2 = *reinterpret_cast<const ulonglong2*>(&As[k * PITCH + r0]);
        acc[0][0] = f32x2_fma(a2.x, w2d[0], acc[0][0]);
        acc[0][1] = f32x2_fma(a2.x, w2d[1], acc[0][1]);
        acc[0][2] = f32x2_fma(a2.x, w2d[2], acc[0][2]);
        acc[0][3] = f32x2_fma(a2.x, w2d[3], acc[0][3]);
        acc[1][0] = f32x2_fma(a2.y, w2d[0], acc[1][0]);
        acc[1][1] = f32x2_fma(a2.y, w2d[1], acc[1][1]);
        acc[1][2] = f32x2_fma(a2.y, w2d[2], acc[1][2]);
        acc[1][3] = f32x2_fma(a2.y, w2d[3], acc[1][3]);
    }

    float bb[4], ww[4];
    #pragma unroll
    for (int q = 0; q < 4; q++) { bb[q] = b1[j0 + q]; ww[q] = w2[j0 + q]; }

    // per-thread partial s for its 4 rows
    float sp[4];
    #pragma unroll
    for (int rp = 0; rp < 2; rp++) {
        float lo[4], hi[4];
        #pragma unroll
        for (int q = 0; q < 4; q++) f32x2_unpack(acc[rp][q], lo[q], hi[q]);
        float sa = 0.f, sb = 0.f;
        #pragma unroll
        for (int q = 0; q < 4; q++) {
            sa += fmaxf(lo[q] + bb[q], 0.f) * ww[q];
            sb += fmaxf(hi[q] + bb[q], 0.f) * ww[q];
        }
        sp[2 * rp] = sa;
        sp[2 * rp + 1] = sb;
    }
    // reduce across the 16 threads sharing these rows (half-warp)
    #pragma unroll
    for (int o = 8; o; o >>= 1) {
        #pragma unroll
        for (int q = 0; q < 4; q++)
            sp[q] += __shfl_down_sync(0xFFFFFFFFu, sp[q], o, 16);
    }
    float m = -INFINITY;
    if (tx == 0) {
        #pragma unroll
        for (int q = 0; q < 4; q++) {
            int row = row0 + r0 + q;
            if (row < n) {
                g_s[row] = sp[q];
                m = fmaxf(m, sp[q]);
            }
        }
    }
    // warp max (lanes 0 and 16 hold values), then block, then global
    m = fmaxf(m, __shfl_down_sync(0xFFFFFFFFu, m, 16));
    if ((tid & 31) == 0 && m > -INFINITY) atomicMax(&blkmax, enc_f(m));
    __syncthreads();
    if (tid == 0) atomicMax(&g_smax_bits, blkmax);
}

// ---------------- aggregation: h_out = relu(mean_{src} hl[src] + hr[dst]) ----------------
__global__ void agg_kernel(const float* __restrict__ hlhr, float* __restrict__ hout)
{
    int w = (blockIdx.x * blockDim.x + threadIdx.x) >> 5;
    int lane = threadIdx.x & 31;
    if (w >= N_NODES) return;
    int s = g_off[w], e = g_off[w + 1];
    float ax = 0.f, ay = 0.f;
    int i = s;
    for (; i + 3 < e; i += 4) {
        int s0 = g_csr[i], s1 = g_csr[i + 1], s2 = g_csr[i + 2], s3 = g_csr[i + 3];
        float2 v0 = *reinterpret_cast<const float2*>(&hlhr[(size_t)s0 * 128 + lane * 2]);
        float2 v1 = *reinterpret_cast<const float2*>(&hlhr[(size_t)s1 * 128 + lane * 2]);
        float2 v2 = *reinterpret_cast<const float2*>(&hlhr[(size_t)s2 * 128 + lane * 2]);
        float2 v3 = *reinterpret_cast<const float2*>(&hlhr[(size_t)s3 * 128 + lane * 2]);
        ax += (v0.x + v1.x) + (v2.x + v3.x);
        ay += (v0.y + v1.y) + (v2.y + v3.y);
    }
    for (; i < e; i++) {
        int s0 = g_csr[i];
        float2 v0 = *reinterpret_cast<const float2*>(&hlhr[(size_t)s0 * 128 + lane * 2]);
        ax += v0.x; ay += v0.y;
    }
    int d = e - s;
    float inv = 1.f / (float)(d > 1 ? d : 1);
    float2 hr = *reinterpret_cast<const float2*>(&hlhr[(size_t)w * 128 + 64 + lane * 2]);
    float ox = fmaxf(ax * inv + hr.x, 0.f);
    float oy = fmaxf(ay * inv + hr.y, 0.f);
    *reinterpret_cast<float2*>(&hout[(size_t)w * 64 + lane * 2]) = make_float2(ox, oy);
}

// ---------------- softmax: exp + partial sums ----------------
__global__ void exp_kernel(const float* __restrict__ pos, float* __restrict__ out)
{
    float gm = dec_f(g_smax_bits);
    float sum = 0.f, sx = 0.f, sy = 0.f;
    for (int i = blockIdx.x * blockDim.x + threadIdx.x; i < N_NODES; i += gridDim.x * blockDim.x) {
        float e = __expf(g_s[i] - gm);
        out[2 + i] = e;
        sum += e;
        sx += e * pos[2 * i];
        sy += e * pos[2 * i + 1];
    }
    __shared__ float sh[3][256];
    sh[0][threadIdx.x] = sum; sh[1][threadIdx.x] = sx; sh[2][threadIdx.x] = sy;
    __syncthreads();
    for (int o = 128; o; o >>= 1) {
        if (threadIdx.x < o) {
            sh[0][threadIdx.x] += sh[0][threadIdx.x + o];
            sh[1][threadIdx.x] += sh[1][threadIdx.x + o];
            sh[2][threadIdx.x] += sh[2][threadIdx.x + o];
        }
        __syncthreads();
    }
    if (threadIdx.x == 0) {
        g_psum[blockIdx.x] = sh[0][0];
        g_psum[256 + blockIdx.x] = sh[1][0];
        g_psum[512 + blockIdx.x] = sh[2][0];
    }
}

// ---------------- norm: every block reduces the 128 partials, then scales its slice
__global__ void norm_kernel(float* __restrict__ out)
{
    __shared__ float sh[3][128];
    int t = threadIdx.x;
    if (t < 128) {
        sh[0][t] = g_psum[t];
        sh[1][t] = g_psum[256 + t];
        sh[2][t] = g_psum[512 + t];
    }
    __syncthreads();
    for (int o = 64; o; o >>= 1) {
        if (t < o) {
            sh[0][t] += sh[0][t + o];
            sh[1][t] += sh[1][t + o];
            sh[2][t] += sh[2][t + o];
        }
        __syncthreads();
    }
    float inv = 1.f / sh[0][0];
    for (int i = blockIdx.x * blockDim.x + t; i < N_NODES; i += gridDim.x * blockDim.x)
        out[2 + i] *= inv;
    if (blockIdx.x == 0 && t == 0) {
        out[0] = sh[1][0] * inv;
        out[1] = sh[2][0] * inv;
    }
}

// ---------------- launcher ----------------
extern "C" void kernel_launch(void* const* d_in, const int* in_sizes, int n_in,
                              void* d_out, int out_size)
{
    const float* x     = (const float*)d_in[0];
    const float* pos   = (const float*)d_in[1];
    const int*   ei    = (const int*)d_in[2];
    const int*   ap    = (const int*)d_in[3];
    const float* rssi  = (const float*)d_in[4];
    const float* emb   = (const float*)d_in[5];
    const float* ew    = (const float*)d_in[6];
    const float* eb    = (const float*)d_in[7];
    const float* Wl0   = (const float*)d_in[8];
    const float* Wr0   = (const float*)d_in[9];
    const float* b0    = (const float*)d_in[10];
    const float* Wl1   = (const float*)d_in[11];
    const float* Wr1   = (const float*)d_in[12];
    const float* b1    = (const float*)d_in[13];
    const float* Wl2   = (const float*)d_in[14];
    const float* Wr2   = (const float*)d_in[15];
    const float* b2    = (const float*)d_in[16];
    const float* sc_w1 = (const float*)d_in[17];
    const float* sc_b1 = (const float*)d_in[18];
    const float* sc_w2 = (const float*)d_in[19];
    const float* sc_b2 = (const float*)d_in[20];
    float* out = (float*)d_out;
    (void)b2; (void)sc_b2;

    const int SM_128_128 = (128 * 68 + 128 * 128) * 4;  // 100352
    const int SM_64_128  = (64 * 68 + 64 * 128) * 4;    // 50176

    cudaFuncSetAttribute(mm_kernel<128, 128>, cudaFuncAttributeMaxDynamicSharedMemorySize, SM_128_128);
    cudaFuncSetAttribute(mm_kernel<64, 128>,  cudaFuncAttributeMaxDynamicSharedMemorySize, SM_64_128);

    float* hlhr; float* h; float* bias0;
    cudaGetSymbolAddress((void**)&hlhr, g_hlhr);
    cudaGetSymbolAddress((void**)&h, g_h);
    cudaGetSymbolAddress((void**)&bias0, g_bias0);

    const int MB = (N_NODES + 63) / 64;            // 782
    const int WB = (N_NODES * 32 + 255) / 256;
    const int EB = (N_EDGES + 255) / 256;

    init_kernel<<<NBS, 256>>>(ap, rssi, emb, ew, eb, Wl0, Wr0, b0);
    hist_kernel<<<EB, 256>>>(ei);
    scan1_kernel<<<NBS, 256>>>();
    scan2_kernel<<<1, 256>>>();
    scan3_kernel<<<NBS, 256>>>();
    fill_kernel<<<EB, 256>>>(ei);

    mm_kernel<128, 128><<<MB, 256, SM_128_128>>>(x, Wl0, Wr0, bias0, bias0 + 64, hlhr, N_NODES);
    agg_kernel<<<WB, 256>>>(hlhr, h);
    mm_kernel<64, 128><<<MB, 256, SM_64_128>>>(h, Wl1, Wr1, nullptr, b1, hlhr, N_NODES);
    agg_kernel<<<WB, 256>>>(hlhr, h);
    mm_kernel<64, 128><<<MB, 256, SM_64_128>>>(h, Wl2, Wr2, nullptr, b2, hlhr, N_NODES);
    agg_kernel<<<WB, 256>>>(hlhr, h);

    mmscore_kernel<<<MB, 256>>>(h, sc_w1, sc_b1, sc_w2, N_NODES);

    exp_kernel<<<128, 256>>>(pos, out);
    norm_kernel<<<196, 256>>>(out);
}